// round 17
// baseline (speedup 1.0000x reference)
#include <cuda_runtime.h>
#include <cuda_bf16.h>
#include <mma.h>

using namespace nvcuda;

#define NR   8192   // rows
#define CIN  512
#define CI   128
#define NB   4096   // value buckets
#define GRP  16     // buckets per group
#define NG   (NB / GRP)   // 256 groups
#define NSG  16           // supergroups (16 groups each)

// ---- scratch (device globals; no allocation allowed) ----
__device__ float d_u[CIN], d_v[CIN];
__device__ float d_cc[2];                 // ca, cb
__device__ float d_a[NR], d_b[NR];
__device__ float d_g[NR * CI];            // 4 MB
__device__ float d_bsv[NR];               // b values in bucketed order
__device__ int   d_si[NR];                // bucketed permutation
__device__ int   d_bstart[NB + 1];
__device__ unsigned d_bmin_ord, d_bmax_ord;
__device__ float d_brange[2];             // lo, scale
__device__ float2 d_T[NG * CI];           // per-group (sum g, sum b*g)
__device__ float2 d_C[NSG * CI];          // coarse supergroup totals (atomic)
__device__ float2 d_SB[(NB + 1) * CI];    // bucket-boundary suffix sums

__device__ __forceinline__ unsigned ford(float f) {           // monotone float->uint
    unsigned b = __float_as_uint(f);
    return b ^ ((unsigned)(((int)b) >> 31) | 0x80000000u);
}
__device__ __forceinline__ float forddec(unsigned e) {
    return __uint_as_float((e & 0x80000000u) ? (e ^ 0x80000000u) : ~e);
}
__device__ __forceinline__ int bidx(float v, float lo, float scale) {
    int i = (int)((v - lo) * scale);                          // trunc: monotone
    return max(0, min(NB - 1, i));
}

// K1: u = Wt @ w1, v = Wp @ w2  (blocks 0-63 warp-per-t; block 64: cc + range init)
__global__ void __launch_bounds__(256) k_uv(const float* __restrict__ Wt,
                                            const float* __restrict__ bt,
                                            const float* __restrict__ Wp,
                                            const float* __restrict__ bp,
                                            const float* __restrict__ wcat) {
    __shared__ float sw[2 * CI];
    int tid = threadIdx.x;
    sw[tid] = wcat[tid];
    __syncthreads();
    if (blockIdx.x < 64) {
        int warp = tid >> 5, lane = tid & 31;
        int t = blockIdx.x * 8 + warp;
        float su = 0.f, sv = 0.f;
        #pragma unroll
        for (int m = 0; m < 4; m++) {
            int o = lane + 32 * m;
            su += Wt[t * CI + o] * sw[o];
            sv += Wp[t * CI + o] * sw[CI + o];
        }
        #pragma unroll
        for (int o = 16; o > 0; o >>= 1) {
            su += __shfl_xor_sync(0xFFFFFFFFu, su, o);
            sv += __shfl_xor_sync(0xFFFFFFFFu, sv, o);
        }
        if (lane == 0) { d_u[t] = su; d_v[t] = sv; }
    } else {
        __shared__ float redA[4], redB[4];
        int warp = tid >> 5, lane = tid & 31;
        float ra = 0.f, rb = 0.f;
        if (tid < CI) {
            ra = bt[tid] * sw[tid];
            rb = bp[tid] * sw[CI + tid];
        }
        #pragma unroll
        for (int o = 16; o > 0; o >>= 1) {
            ra += __shfl_xor_sync(0xFFFFFFFFu, ra, o);
            rb += __shfl_xor_sync(0xFFFFFFFFu, rb, o);
        }
        if (lane == 0 && warp < 4) { redA[warp] = ra; redB[warp] = rb; }
        __syncthreads();
        if (tid == 0) {
            d_cc[0] = redA[0] + redA[1] + redA[2] + redA[3];
            d_cc[1] = redB[0] + redB[1] + redB[2] + redB[3];
            d_bmin_ord = 0xFFFFFFFFu;      // re-init every launch (graph replay)
            d_bmax_ord = 0u;
        }
    }
}

// K2: a[i], b[i] + block min/max of b   (warp per row; 1024 blocks x 256)
__global__ void __launch_bounds__(256) k_ab(const float* __restrict__ x) {
    __shared__ float su[CIN], sv[CIN];
    __shared__ float sbv8[8];
    int tid = threadIdx.x;
    for (int i = tid; i < CIN; i += 256) { su[i] = d_u[i]; sv[i] = d_v[i]; }
    __syncthreads();
    int warp = tid >> 5, lane = tid & 31;
    int row = blockIdx.x * 8 + warp;
    const float4* xr4 = (const float4*)(x + row * CIN);
    const float4* su4 = (const float4*)su;
    const float4* sv4 = (const float4*)sv;
    float sa = 0.f, sb = 0.f;
    #pragma unroll
    for (int m = 0; m < 4; m++) {
        int j = lane + 32 * m;
        float4 xv = xr4[j];
        float4 uu = su4[j];
        float4 vv = sv4[j];
        sa += xv.x * uu.x + xv.y * uu.y + xv.z * uu.z + xv.w * uu.w;
        sb += xv.x * vv.x + xv.y * vv.y + xv.z * vv.z + xv.w * vv.w;
    }
    #pragma unroll
    for (int o = 16; o > 0; o >>= 1) {
        sa += __shfl_xor_sync(0xFFFFFFFFu, sa, o);
        sb += __shfl_xor_sync(0xFFFFFFFFu, sb, o);
    }
    if (lane == 0) {
        float bvv = sb + d_cc[1];
        d_a[row] = sa + d_cc[0];
        d_b[row] = bvv;
        sbv8[warp] = bvv;
    }
    __syncthreads();
    if (tid == 0) {
        float mn = sbv8[0], mx = sbv8[0];
        #pragma unroll
        for (int q = 1; q < 8; q++) { mn = fminf(mn, sbv8[q]); mx = fmaxf(mx, sbv8[q]); }
        atomicMin(&d_bmin_ord, ford(mn));
        atomicMax(&d_bmax_ord, ford(mx));
    }
}

// K3: g = x @ Wg + bg via wmma bf16 split: (xh+xl)(wh+wl) ~ hh + hl + lh.
// 128 CTAs x 256 thr; CTA tile 64x128, warp tile 32x32, K chunks of 32.
// Reg-prefetch + smem double-buffer (one barrier pair per chunk).
#define KG_BUF 24576        // per-buffer bytes: AH 4K | AL 4K | BH 8K | BL 8K
#define KG_SMEM (2 * KG_BUF)
__global__ void __launch_bounds__(256, 1) k_g(const float* __restrict__ x,
                                              const float* __restrict__ Wg,
                                              const float* __restrict__ bg) {
    extern __shared__ char smem[];
    int tid = threadIdx.x;
    int wid = tid >> 5;
    int warpM = wid & 1;          // 2 warps over M (32 rows each)
    int warpN = wid >> 1;         // 4 warps over N (32 cols each)
    int bm = blockIdx.x * 64;

    wmma::fragment<wmma::accumulator, 16, 16, 16, float> fc[2][2];
    #pragma unroll
    for (int mi = 0; mi < 2; mi++)
        #pragma unroll
        for (int ni = 0; ni < 2; ni++) wmma::fill_fragment(fc[mi][ni], 0.0f);

    // prefetch chunk 0: x tile 64x32 (512 float4, 2/thr), W tile 32x128 (1024 float4, 4/thr)
    float4 xa[2], wv[4];
    #pragma unroll
    for (int j = 0; j < 2; j++) {
        int p = tid + j * 256, row = p >> 3, k4 = p & 7;
        xa[j] = *(const float4*)(x + (bm + row) * CIN + k4 * 4);
    }
    #pragma unroll
    for (int j = 0; j < 4; j++) {
        int p = tid + j * 256, kr = p >> 5, n4 = p & 31;
        wv[j] = *(const float4*)(Wg + kr * CI + n4 * 4);
    }

    #pragma unroll 1
    for (int c = 0; c < CIN / 32; c++) {
        char* base = smem + (c & 1) * KG_BUF;
        __nv_bfloat16* AH = (__nv_bfloat16*)(base);
        __nv_bfloat16* AL = (__nv_bfloat16*)(base + 4096);
        __nv_bfloat16* BH = (__nv_bfloat16*)(base + 8192);
        __nv_bfloat16* BL = (__nv_bfloat16*)(base + 16384);
        // stage regs -> smem (hi/lo split)
        #pragma unroll
        for (int j = 0; j < 2; j++) {
            int p = tid + j * 256, row = p >> 3, k4 = p & 7;
            float vv[4] = {xa[j].x, xa[j].y, xa[j].z, xa[j].w};
            __nv_bfloat16 h[4], l[4];
            #pragma unroll
            for (int q = 0; q < 4; q++) {
                h[q] = __float2bfloat16(vv[q]);
                l[q] = __float2bfloat16(vv[q] - __bfloat162float(h[q]));
            }
            __nv_bfloat162 hp0 = __halves2bfloat162(h[0], h[1]);
            __nv_bfloat162 hp1 = __halves2bfloat162(h[2], h[3]);
            __nv_bfloat162 lp0 = __halves2bfloat162(l[0], l[1]);
            __nv_bfloat162 lp1 = __halves2bfloat162(l[2], l[3]);
            *(uint2*)(AH + row * 32 + k4 * 4) = make_uint2(*(unsigned*)&hp0, *(unsigned*)&hp1);
            *(uint2*)(AL + row * 32 + k4 * 4) = make_uint2(*(unsigned*)&lp0, *(unsigned*)&lp1);
        }
        #pragma unroll
        for (int j = 0; j < 4; j++) {
            int p = tid + j * 256, kr = p >> 5, n4 = p & 31;
            float vv[4] = {wv[j].x, wv[j].y, wv[j].z, wv[j].w};
            __nv_bfloat16 h[4], l[4];
            #pragma unroll
            for (int q = 0; q < 4; q++) {
                h[q] = __float2bfloat16(vv[q]);
                l[q] = __float2bfloat16(vv[q] - __bfloat162float(h[q]));
            }
            __nv_bfloat162 hp0 = __halves2bfloat162(h[0], h[1]);
            __nv_bfloat162 hp1 = __halves2bfloat162(h[2], h[3]);
            __nv_bfloat162 lp0 = __halves2bfloat162(l[0], l[1]);
            __nv_bfloat162 lp1 = __halves2bfloat162(l[2], l[3]);
            *(uint2*)(BH + kr * CI + n4 * 4) = make_uint2(*(unsigned*)&hp0, *(unsigned*)&hp1);
            *(uint2*)(BL + kr * CI + n4 * 4) = make_uint2(*(unsigned*)&lp0, *(unsigned*)&lp1);
        }
        __syncthreads();
        // prefetch next chunk (overlaps with MMA below)
        if (c + 1 < CIN / 32) {
            int k0 = (c + 1) * 32;
            #pragma unroll
            for (int j = 0; j < 2; j++) {
                int p = tid + j * 256, row = p >> 3, k4 = p & 7;
                xa[j] = *(const float4*)(x + (bm + row) * CIN + k0 + k4 * 4);
            }
            #pragma unroll
            for (int j = 0; j < 4; j++) {
                int p = tid + j * 256, kr = p >> 5, n4 = p & 31;
                wv[j] = *(const float4*)(Wg + (k0 + kr) * CI + n4 * 4);
            }
        }
        // compute: 2 k-steps of 16
        #pragma unroll
        for (int ks = 0; ks < 2; ks++) {
            wmma::fragment<wmma::matrix_a, 16, 16, 16, __nv_bfloat16, wmma::row_major> ah[2], al[2];
            wmma::fragment<wmma::matrix_b, 16, 16, 16, __nv_bfloat16, wmma::row_major> bh[2], bl[2];
            #pragma unroll
            for (int mi = 0; mi < 2; mi++) {
                const __nv_bfloat16* pa = AH + (warpM * 32 + mi * 16) * 32 + ks * 16;
                const __nv_bfloat16* pl = AL + (warpM * 32 + mi * 16) * 32 + ks * 16;
                wmma::load_matrix_sync(ah[mi], pa, 32);
                wmma::load_matrix_sync(al[mi], pl, 32);
            }
            #pragma unroll
            for (int ni = 0; ni < 2; ni++) {
                const __nv_bfloat16* pb = BH + (ks * 16) * CI + warpN * 32 + ni * 16;
                const __nv_bfloat16* pl = BL + (ks * 16) * CI + warpN * 32 + ni * 16;
                wmma::load_matrix_sync(bh[ni], pb, CI);
                wmma::load_matrix_sync(bl[ni], pl, CI);
            }
            #pragma unroll
            for (int mi = 0; mi < 2; mi++)
                #pragma unroll
                for (int ni = 0; ni < 2; ni++) {
                    wmma::mma_sync(fc[mi][ni], ah[mi], bh[ni], fc[mi][ni]);
                    wmma::mma_sync(fc[mi][ni], ah[mi], bl[ni], fc[mi][ni]);
                    wmma::mma_sync(fc[mi][ni], al[mi], bh[ni], fc[mi][ni]);
                }
        }
        __syncthreads();
    }
    // epilogue: frags -> smem f32 (reuse buffers), bias add, vectorized store
    float* es = (float*)smem;     // 64 x 128 f32 = 32 KB
    #pragma unroll
    for (int mi = 0; mi < 2; mi++)
        #pragma unroll
        for (int ni = 0; ni < 2; ni++)
            wmma::store_matrix_sync(es + (warpM * 32 + mi * 16) * CI + warpN * 32 + ni * 16,
                                    fc[mi][ni], CI, wmma::mem_row_major);
    __syncthreads();
    #pragma unroll
    for (int j = 0; j < 8; j++) {
        int p = tid + j * 256, row = p >> 5, n4 = p & 31;
        float4 o = *(float4*)(es + row * CI + n4 * 4);
        float4 bb = *(const float4*)(bg + n4 * 4);
        o.x += bb.x; o.y += bb.y; o.z += bb.z; o.w += bb.w;
        *(float4*)(d_g + (bm + row) * CI + n4 * 4) = o;
    }
}

// K4: counting-sort b into NB value buckets (1 block, 1024 threads).
__global__ void __launch_bounds__(1024) k_bucket() {
    __shared__ int hist[NB];
    __shared__ int scanbuf[1024];
    __shared__ float sls[2];
    int tid = threadIdx.x;
    #pragma unroll
    for (int q = 0; q < NB / 1024; q++) hist[tid + 1024 * q] = 0;
    {
        float* cz = (float*)d_C;
        #pragma unroll
        for (int q = 0; q < (NSG * CI * 2) / 1024; q++) cz[tid + 1024 * q] = 0.f;
    }
    if (tid == 0) {
        float lo = forddec(d_bmin_ord);
        float hi = forddec(d_bmax_ord);
        float d = hi - lo;
        float scale = (d > 0.f) ? ((float)NB / d) : 0.f;
        sls[0] = lo; sls[1] = scale;
        d_brange[0] = lo; d_brange[1] = scale;
    }
    __syncthreads();
    float lo = sls[0], scale = sls[1];
    for (int j = tid; j < NR; j += 1024)
        atomicAdd(&hist[bidx(d_b[j], lo, scale)], 1);
    __syncthreads();
    int h0 = hist[4 * tid], h1 = hist[4 * tid + 1];
    int h2 = hist[4 * tid + 2], h3 = hist[4 * tid + 3];
    int tot = h0 + h1 + h2 + h3;
    scanbuf[tid] = tot;
    __syncthreads();
    #pragma unroll
    for (int off = 1; off < 1024; off <<= 1) {
        int v = (tid >= off) ? scanbuf[tid - off] : 0;
        __syncthreads();
        scanbuf[tid] += v;
        __syncthreads();
    }
    int excl = scanbuf[tid] - tot;
    d_bstart[4 * tid]     = excl;
    d_bstart[4 * tid + 1] = excl + h0;
    d_bstart[4 * tid + 2] = excl + h0 + h1;
    d_bstart[4 * tid + 3] = excl + h0 + h1 + h2;
    hist[4 * tid]     = excl;
    hist[4 * tid + 1] = excl + h0;
    hist[4 * tid + 2] = excl + h0 + h1;
    hist[4 * tid + 3] = excl + h0 + h1 + h2;
    if (tid == 0) d_bstart[NB] = NR;
    __syncthreads();
    for (int j = tid; j < NR; j += 1024) {
        float bv = d_b[j];
        int pos = atomicAdd(&hist[bidx(bv, lo, scale)], 1);
        d_si[pos] = j;
        d_bsv[pos] = bv;
    }
}

// K5: per-group totals (float2) + atomic coarse supergroup totals  (NG blocks x 128)
__global__ void __launch_bounds__(CI) k_segsum() {
    __shared__ int ssi[CI];
    __shared__ float sbv[CI];
    int g = blockIdx.x, c = threadIdx.x;
    int pstart = d_bstart[g * GRP];
    int pend   = d_bstart[g * GRP + GRP];
    float t1 = 0.f, t2 = 0.f;
    for (int base = pstart; base < pend; base += CI) {
        int nchunk = min(CI, pend - base);
        if (c < nchunk) { ssi[c] = d_si[base + c]; sbv[c] = d_bsv[base + c]; }
        __syncthreads();
        for (int m = 0; m < nchunk; m++) {
            float gv = d_g[ssi[m] * CI + c];
            t1 += gv;
            t2 += sbv[m] * gv;
        }
        __syncthreads();
    }
    d_T[g * CI + c] = make_float2(t1, t2);
    int sg = g >> 4;
    atomicAdd(&d_C[sg * CI + c].x, t1);
    atomicAdd(&d_C[sg * CI + c].y, t2);
}

// K6: bucket-boundary suffix sums (NG blocks x 128).
__global__ void __launch_bounds__(CI) k_psum() {
    int g = blockIdx.x, c = threadIdx.x;
    int sg = g >> 4;
    float a1 = 0.f, a2 = 0.f;
    #pragma unroll 4
    for (int s = sg + 1; s < NSG; s++) {
        float2 cv = d_C[s * CI + c];
        a1 += cv.x; a2 += cv.y;
    }
    int gend = (sg + 1) * 16;
    #pragma unroll 4
    for (int gp = g + 1; gp < gend; gp++) {
        float2 tv = d_T[gp * CI + c];
        a1 += tv.x; a2 += tv.y;
    }
    for (int bk = GRP - 1; bk >= 0; bk--) {
        int gb = g * GRP + bk;
        d_SB[(gb + 1) * CI + c] = make_float2(a1, a2);
        int ps = d_bstart[gb], pe = d_bstart[gb + 1];
        for (int pos = ps; pos < pe; pos++) {
            int j = d_si[pos];
            float bv = d_bsv[pos];
            float gv = d_g[j * CI + c];
            a1 += gv;
            a2 += bv * gv;
        }
    }
}

// K7: z_i = (a_i*S1 + S2)/N; S = bucket suffix + exact boundary-bucket members
__global__ void __launch_bounds__(256) k_out(float* __restrict__ z) {
    int tid = threadIdx.x;
    int half = tid >> 7, c = tid & 127;
    int row = blockIdx.x * 2 + half;
    float av = d_a[row];
    float t = -av;
    float lo = d_brange[0], scale = d_brange[1];
    int bt = bidx(t, lo, scale);
    float2 sv = d_SB[(bt + 1) * CI + c];
    float s1 = sv.x, s2 = sv.y;
    int ps = d_bstart[bt], pe = d_bstart[bt + 1];
    for (int pos = ps; pos < pe; pos++) {
        float bv = d_bsv[pos];
        if (bv > t) {
            float gv = d_g[d_si[pos] * CI + c];
            s1 += gv;
            s2 += bv * gv;
        }
    }
    z[row * CI + c] = (av * s1 + s2) * (1.0f / (float)NR);
}

extern "C" void kernel_launch(void* const* d_in, const int* in_sizes, int n_in,
                              void* d_out, int out_size) {
    const float* x    = (const float*)d_in[0];
    const float* Wg   = (const float*)d_in[1];
    const float* bg   = (const float*)d_in[2];
    const float* Wt   = (const float*)d_in[3];
    const float* bt   = (const float*)d_in[4];
    const float* Wp   = (const float*)d_in[5];
    const float* bp   = (const float*)d_in[6];
    const float* wcat = (const float*)d_in[7];
    float* z = (float*)d_out;

    cudaFuncSetAttribute(k_g, cudaFuncAttributeMaxDynamicSharedMemorySize, KG_SMEM);

    k_uv<<<65, 256>>>(Wt, bt, Wp, bp, wcat);
    k_ab<<<NR / 8, 256>>>(x);
    k_bucket<<<1, 1024>>>();
    k_g<<<NR / 64, 256, KG_SMEM>>>(x, Wg, bg);
    k_segsum<<<NG, CI>>>();
    k_psum<<<NG, CI>>>();
    k_out<<<NR / 2, 256>>>(z);
}